// round 1
// baseline (speedup 1.0000x reference)
#include <cuda_runtime.h>
#include <math.h>

#define Nn 100000
#define Ee 1600000
#define NSB 196   // ceil(Nn/512)

// ---------------- scratch (device globals — no allocation allowed) ----------
__device__ int   g_rowptr[Nn + 1];
__device__ int   g_cursor[Nn];
__device__ int   g_colidx[Ee];
__device__ int   g_bsum[NSB];
__device__ int   g_is64;
__device__ float g_mean[(size_t)Nn * 64];
__device__ float g_out [(size_t)Nn * 64];
__device__ float g_h   [(size_t)Nn * 64];
__device__ float g_bnsum[64];
__device__ float g_bnsq [64];

// ---------------- edge-index dtype detection --------------------------------
__global__ void k_detect(const void* ei) {
    if (threadIdx.x == 0 && blockIdx.x == 0) {
        // If data is int32, reading as int64 combines two node ids: the high
        // 32 bits are a random id in [0,100000) -> value >= 2^32 with
        // probability 1-1e-5 per probe. 32 probes => certain detection.
        const long long* q = (const long long*)ei;
        int ok = 1;
        #pragma unroll 1
        for (int i = 0; i < 32; i++) {
            long long v = q[(long long)i * 33331];   // stays < Ee int64 slots
            if (v < 0 || v >= Nn) { ok = 0; break; }
        }
        g_is64 = ok;
    }
}

__device__ __forceinline__ int edge_at(const void* ei, long long i, int is64) {
    return is64 ? (int)((const long long*)ei)[i] : ((const int*)ei)[i];
}

// ---------------- CSR build --------------------------------------------------
__global__ void k_zero_counts() {
    int i = blockIdx.x * blockDim.x + threadIdx.x;
    if (i < Nn) g_cursor[i] = 0;
}

__global__ void k_hist(const void* ei) {
    int is64 = g_is64;
    long long stride = (long long)gridDim.x * blockDim.x;
    for (long long e = blockIdx.x * (long long)blockDim.x + threadIdx.x; e < Ee; e += stride) {
        int d = edge_at(ei, Ee + e, is64);   // dst row
        atomicAdd(&g_cursor[d], 1);
    }
}

__global__ void k_scan1() {
    __shared__ int sh[512];
    int i = blockIdx.x * 512 + threadIdx.x;
    int v = (i < Nn) ? g_cursor[i] : 0;
    sh[threadIdx.x] = v;
    __syncthreads();
    for (int off = 1; off < 512; off <<= 1) {
        int t = (threadIdx.x >= off) ? sh[threadIdx.x - off] : 0;
        __syncthreads();
        sh[threadIdx.x] += t;
        __syncthreads();
    }
    if (i < Nn) g_rowptr[i + 1] = sh[threadIdx.x];   // block-local inclusive
    if (threadIdx.x == 511) g_bsum[blockIdx.x] = sh[511];
}

__global__ void k_scan2() {
    if (threadIdx.x == 0) {
        int acc = 0;
        for (int b = 0; b < NSB; b++) { int t = g_bsum[b]; g_bsum[b] = acc; acc += t; }
    }
}

__global__ void k_scan3() {
    int i = blockIdx.x * blockDim.x + threadIdx.x;
    if (i < Nn) g_rowptr[i + 1] += g_bsum[i >> 9];
    if (i == 0) g_rowptr[0] = 0;
}

__global__ void k_fillcur() {
    int i = blockIdx.x * blockDim.x + threadIdx.x;
    if (i < Nn) g_cursor[i] = g_rowptr[i];
}

__global__ void k_scatter(const void* ei) {
    int is64 = g_is64;
    long long stride = (long long)gridDim.x * blockDim.x;
    for (long long e = blockIdx.x * (long long)blockDim.x + threadIdx.x; e < Ee; e += stride) {
        int d = edge_at(ei, Ee + e, is64);
        int s = edge_at(ei, e,      is64);
        int pos = atomicAdd(&g_cursor[d], 1);
        g_colidx[pos] = s;
    }
}

// ---------------- mean aggregation: warp per node ----------------------------
// in = feature table (x or g_h); writes per-node mean into g_mean.
__global__ void k_agg(const float* __restrict__ in, int use_gh) {
    const float* __restrict__ p = use_gh ? g_h : in;
    int gt = blockIdx.x * blockDim.x + threadIdx.x;
    int w = gt >> 5, lane = gt & 31;
    if (w >= Nn) return;
    int beg = g_rowptr[w], end = g_rowptr[w + 1];
    float ax = 0.f, ay = 0.f;
    for (int e = beg; e < end; e += 32) {
        int cnt = min(32, end - e);
        int s = (lane < cnt) ? __ldg(&g_colidx[e + lane]) : 0;
        for (int j = 0; j < cnt; j++) {
            int sj = __shfl_sync(0xffffffffu, s, j);
            float2 v = __ldg((const float2*)(p + (size_t)sj * 64) + lane);
            ax += v.x; ay += v.y;
        }
    }
    float inv = 1.0f / (float)max(end - beg, 1);
    ((float2*)g_mean)[(size_t)w * 32 + lane] = make_float2(ax * inv, ay * inv);
}

// ---------------- fused dual-GEMM (64->64) + L2 normalize --------------------
// out = mean @ Wl^T + hin @ Wr^T + b ; L2 normalize row ; write g_out
__global__ void __launch_bounds__(256) k_gemm64(const float* __restrict__ hin, int use_gh,
                                                const float* __restrict__ Wl,
                                                const float* __restrict__ Wr,
                                                const float* __restrict__ b) {
    __shared__ float sWl[64 * 64];   // transposed: sWl[k*64 + j] = Wl[j][k]
    __shared__ float sWr[64 * 64];
    __shared__ float sb[64];
    for (int i = threadIdx.x; i < 64 * 64; i += 256) {
        int j = i >> 6, k = i & 63;
        sWl[k * 64 + j] = Wl[i];
        sWr[k * 64 + j] = Wr[i];
    }
    if (threadIdx.x < 64) sb[threadIdx.x] = b[threadIdx.x];
    __syncthreads();

    const float* __restrict__ hp = use_gh ? g_h : hin;
    int r = blockIdx.x * 256 + threadIdx.x;
    if (r >= Nn) return;

    float acc[64];
    #pragma unroll
    for (int j = 0; j < 64; j++) acc[j] = sb[j];

    const float4* m4 = (const float4*)(g_mean + (size_t)r * 64);
    const float4* h4 = (const float4*)(hp + (size_t)r * 64);
    #pragma unroll 1
    for (int k4 = 0; k4 < 16; k4++) {
        float4 m = __ldg(m4 + k4), h = __ldg(h4 + k4);
        #pragma unroll
        for (int kk = 0; kk < 4; kk++) {
            float mv = kk == 0 ? m.x : kk == 1 ? m.y : kk == 2 ? m.z : m.w;
            float hv = kk == 0 ? h.x : kk == 1 ? h.y : kk == 2 ? h.z : h.w;
            int k = k4 * 4 + kk;
            const float4* wl4 = (const float4*)(sWl + k * 64);
            const float4* wr4 = (const float4*)(sWr + k * 64);
            #pragma unroll
            for (int j4 = 0; j4 < 16; j4++) {
                float4 a = wl4[j4], c = wr4[j4];
                acc[j4 * 4 + 0] += mv * a.x + hv * c.x;
                acc[j4 * 4 + 1] += mv * a.y + hv * c.y;
                acc[j4 * 4 + 2] += mv * a.z + hv * c.z;
                acc[j4 * 4 + 3] += mv * a.w + hv * c.w;
            }
        }
    }
    float s = 0.f;
    #pragma unroll
    for (int j = 0; j < 64; j++) s += acc[j] * acc[j];
    float sc = 1.0f / fmaxf(sqrtf(s), 1e-12f);
    float4* o4 = (float4*)(g_out + (size_t)r * 64);
    #pragma unroll
    for (int j4 = 0; j4 < 16; j4++)
        o4[j4] = make_float4(acc[j4 * 4 + 0] * sc, acc[j4 * 4 + 1] * sc,
                             acc[j4 * 4 + 2] * sc, acc[j4 * 4 + 3] * sc);
}

// ---------------- final layer: dual GEMM 64 -> 10, no normalize --------------
__global__ void __launch_bounds__(256) k_gemm10(const float* __restrict__ Wl,
                                                const float* __restrict__ Wr,
                                                const float* __restrict__ b,
                                                float* __restrict__ out) {
    __shared__ float sWl[64 * 10];   // sWl[k*10 + j] = Wl[j][k]
    __shared__ float sWr[64 * 10];
    __shared__ float sb[10];
    for (int i = threadIdx.x; i < 640; i += 256) {
        int j = i / 64, k = i % 64;
        sWl[k * 10 + j] = Wl[i];
        sWr[k * 10 + j] = Wr[i];
    }
    if (threadIdx.x < 10) sb[threadIdx.x] = b[threadIdx.x];
    __syncthreads();

    int r = blockIdx.x * 256 + threadIdx.x;
    if (r >= Nn) return;

    float acc[10];
    #pragma unroll
    for (int j = 0; j < 10; j++) acc[j] = sb[j];

    const float4* m4 = (const float4*)(g_mean + (size_t)r * 64);
    const float4* h4 = (const float4*)(g_h + (size_t)r * 64);
    #pragma unroll 1
    for (int k4 = 0; k4 < 16; k4++) {
        float4 m = __ldg(m4 + k4), h = __ldg(h4 + k4);
        #pragma unroll
        for (int kk = 0; kk < 4; kk++) {
            float mv = kk == 0 ? m.x : kk == 1 ? m.y : kk == 2 ? m.z : m.w;
            float hv = kk == 0 ? h.x : kk == 1 ? h.y : kk == 2 ? h.z : h.w;
            int k = k4 * 4 + kk;
            #pragma unroll
            for (int j = 0; j < 10; j++)
                acc[j] += mv * sWl[k * 10 + j] + hv * sWr[k * 10 + j];
        }
    }
    #pragma unroll
    for (int j = 0; j < 10; j++) out[(size_t)r * 10 + j] = acc[j];
}

// ---------------- batchnorm --------------------------------------------------
__global__ void k_zerobn() {
    if (threadIdx.x < 64) { g_bnsum[threadIdx.x] = 0.f; g_bnsq[threadIdx.x] = 0.f; }
}

__global__ void k_bnstats() {
    // blockDim=256 => grid stride is a multiple of 64 => column fixed per thread
    int tid = blockIdx.x * blockDim.x + threadIdx.x;
    long long stride = (long long)gridDim.x * blockDim.x;
    int col = tid & 63;
    float s = 0.f, q = 0.f;
    for (long long i = tid; i < (long long)Nn * 64; i += stride) {
        float x = g_out[i];
        s += x; q += x * x;
    }
    atomicAdd(&g_bnsum[col], s);
    atomicAdd(&g_bnsq[col], q);
}

__global__ void k_bnapply(const float* __restrict__ gamma, const float* __restrict__ beta) {
    __shared__ float ssc[64], ssh[64];
    if (threadIdx.x < 64) {
        float mu  = g_bnsum[threadIdx.x] * (1.0f / Nn);
        float var = g_bnsq[threadIdx.x] * (1.0f / Nn) - mu * mu;
        float sc  = rsqrtf(var + 1e-5f) * gamma[threadIdx.x];
        ssc[threadIdx.x] = sc;
        ssh[threadIdx.x] = beta[threadIdx.x] - mu * sc;
    }
    __syncthreads();
    long long stride = (long long)gridDim.x * blockDim.x;
    for (long long i = blockIdx.x * (long long)blockDim.x + threadIdx.x;
         i < (long long)Nn * 64; i += stride) {
        int col = (int)(i & 63);
        float y = g_out[i] * ssc[col] + ssh[col];
        g_h[i] = fmaxf(y, 0.0f);
    }
}

// ---------------- launch -----------------------------------------------------
extern "C" void kernel_launch(void* const* d_in, const int* in_sizes, int n_in,
                              void* d_out, int out_size) {
    const float* x   = (const float*)d_in[0];
    const void*  ei  = d_in[1];
    const float* Wl1 = (const float*)d_in[2];
    const float* Wr1 = (const float*)d_in[3];
    const float* b1  = (const float*)d_in[4];
    const float* g1  = (const float*)d_in[5];
    const float* be1 = (const float*)d_in[6];
    const float* Wl2 = (const float*)d_in[7];
    const float* Wr2 = (const float*)d_in[8];
    const float* b2  = (const float*)d_in[9];
    const float* g2  = (const float*)d_in[10];
    const float* be2 = (const float*)d_in[11];
    const float* Wl3 = (const float*)d_in[12];
    const float* Wr3 = (const float*)d_in[13];
    const float* b3  = (const float*)d_in[14];
    float* out = (float*)d_out;

    const int NBLK_N   = (Nn + 255) / 256;      // 391
    const int NBLK_AGG = (Nn * 32 + 255) / 256; // 12500
    const int NBLK_E   = 2048;
    const int NBLK_EW  = 592;                   // elementwise / stats

    // CSR build (per launch; graph replays it — deterministic work)
    k_detect     <<<1, 32>>>(ei);
    k_zero_counts<<<NBLK_N, 256>>>();
    k_hist       <<<NBLK_E, 256>>>(ei);
    k_scan1      <<<NSB, 512>>>();
    k_scan2      <<<1, 32>>>();
    k_scan3      <<<NBLK_N, 256>>>();
    k_fillcur    <<<NBLK_N, 256>>>();
    k_scatter    <<<NBLK_E, 256>>>(ei);

    // Layer 1
    k_agg    <<<NBLK_AGG, 256>>>(x, 0);
    k_gemm64 <<<NBLK_N, 256>>>(x, 0, Wl1, Wr1, b1);
    k_zerobn <<<1, 64>>>();
    k_bnstats<<<NBLK_EW, 256>>>();
    k_bnapply<<<NBLK_EW, 256>>>(g1, be1);

    // Layer 2
    k_agg    <<<NBLK_AGG, 256>>>(nullptr, 1);
    k_gemm64 <<<NBLK_N, 256>>>(nullptr, 1, Wl2, Wr2, b2);
    k_zerobn <<<1, 64>>>();
    k_bnstats<<<NBLK_EW, 256>>>();
    k_bnapply<<<NBLK_EW, 256>>>(g2, be2);

    // Layer 3 (no normalize, no BN) — writes d_out
    k_agg    <<<NBLK_AGG, 256>>>(nullptr, 1);
    k_gemm10 <<<NBLK_N, 256>>>(Wl3, Wr3, b3, out);
}

// round 2
// speedup vs baseline: 1.0895x; 1.0895x over previous
#include <cuda_runtime.h>
#include <math.h>

#define Nn 100000
#define Ee 1600000
#define NSB 196   // ceil(Nn/512)

typedef unsigned long long ull;

// ---------------- scratch (device globals — no allocation allowed) ----------
__device__ int   g_rowptr[Nn + 1];
__device__ int   g_cursor[Nn];
__device__ int   g_colidx[Ee];
__device__ int   g_bsum[NSB];
__device__ int   g_is64;
__device__ float g_mean[(size_t)Nn * 64];   // also reused as z (N x 16) in layer 3
__device__ float g_out [(size_t)Nn * 64];
__device__ float g_h   [(size_t)Nn * 64];
__device__ float g_bnsum[64];
__device__ float g_bnsq [64];

// ---------------- f32x2 packed helpers ---------------------------------------
__device__ __forceinline__ ull pack2(float v) {
    ull r; asm("mov.b64 %0, {%1, %1};" : "=l"(r) : "f"(v)); return r;
}
__device__ __forceinline__ ull fma2(ull a, ull b, ull c) {
    ull d; asm("fma.rn.f32x2 %0, %1, %2, %3;" : "=l"(d) : "l"(a), "l"(b), "l"(c)); return d;
}
__device__ __forceinline__ void unpack2(ull v, float& lo, float& hi) {
    asm("mov.b64 {%0, %1}, %2;" : "=f"(lo), "=f"(hi) : "l"(v));
}

// ---------------- edge-index dtype detection (parallel) ----------------------
__global__ void k_detect(const void* ei) {
    int lane = threadIdx.x;
    const long long* q = (const long long*)ei;
    long long v = q[(long long)lane * 33331];    // max 1,033,261 < Ee int64 slots
    unsigned bad = __ballot_sync(0xffffffffu, v < 0 || v >= Nn);
    if (lane == 0) g_is64 = (bad == 0) ? 1 : 0;
}

__device__ __forceinline__ int edge_at(const void* ei, long long i, int is64) {
    return is64 ? (int)__ldg(&((const long long*)ei)[i]) : __ldg(&((const int*)ei)[i]);
}

// ---------------- CSR build --------------------------------------------------
__global__ void k_zero_counts() {
    int i = blockIdx.x * blockDim.x + threadIdx.x;
    if (i < Nn) g_cursor[i] = 0;
}

__global__ void k_hist(const void* ei) {
    int is64 = g_is64;
    long long stride = (long long)gridDim.x * blockDim.x;
    for (long long e = blockIdx.x * (long long)blockDim.x + threadIdx.x; e < Ee; e += stride) {
        int d = edge_at(ei, Ee + e, is64);   // dst row
        atomicAdd(&g_cursor[d], 1);
    }
}

__global__ void k_scan1() {
    __shared__ int sh[512];
    int i = blockIdx.x * 512 + threadIdx.x;
    int v = (i < Nn) ? g_cursor[i] : 0;
    sh[threadIdx.x] = v;
    __syncthreads();
    for (int off = 1; off < 512; off <<= 1) {
        int t = (threadIdx.x >= off) ? sh[threadIdx.x - off] : 0;
        __syncthreads();
        sh[threadIdx.x] += t;
        __syncthreads();
    }
    if (i < Nn) g_rowptr[i + 1] = sh[threadIdx.x];   // block-local inclusive
    if (threadIdx.x == 511) g_bsum[blockIdx.x] = sh[511];
}

// parallel exclusive scan of g_bsum[0..NSB) in one block
__global__ void k_scan2b() {
    __shared__ int sh[256];
    int tid = threadIdx.x;
    int v = (tid < NSB) ? g_bsum[tid] : 0;
    sh[tid] = v;
    __syncthreads();
    for (int off = 1; off < 256; off <<= 1) {
        int t = (tid >= off) ? sh[tid - off] : 0;
        __syncthreads();
        sh[tid] += t;
        __syncthreads();
    }
    if (tid < NSB) g_bsum[tid] = sh[tid] - v;   // exclusive
}

__global__ void k_scan3() {
    int i = blockIdx.x * blockDim.x + threadIdx.x;
    if (i < Nn) g_rowptr[i + 1] += g_bsum[i >> 9];
    if (i == 0) g_rowptr[0] = 0;
}

__global__ void k_fillcur() {
    int i = blockIdx.x * blockDim.x + threadIdx.x;
    if (i < Nn) g_cursor[i] = g_rowptr[i];
}

__global__ void k_scatter(const void* ei) {
    int is64 = g_is64;
    long long stride = (long long)gridDim.x * blockDim.x;
    for (long long e = blockIdx.x * (long long)blockDim.x + threadIdx.x; e < Ee; e += stride) {
        int d = edge_at(ei, Ee + e, is64);
        int s = edge_at(ei, e,      is64);
        int pos = atomicAdd(&g_cursor[d], 1);
        g_colidx[pos] = s;
    }
}

// ---------------- mean aggregation (64-wide rows): warp per node -------------
__global__ void k_agg(const float* __restrict__ in, int use_gh) {
    const float* __restrict__ p = use_gh ? g_h : in;
    int gt = blockIdx.x * blockDim.x + threadIdx.x;
    int w = gt >> 5, lane = gt & 31;
    if (w >= Nn) return;
    int beg = g_rowptr[w], end = g_rowptr[w + 1];
    float ax = 0.f, ay = 0.f;
    for (int e = beg; e < end; e += 32) {
        int cnt = min(32, end - e);
        int s = (lane < cnt) ? __ldg(&g_colidx[e + lane]) : 0;
        int j = 0;
        for (; j + 4 <= cnt; j += 4) {
            int s0 = __shfl_sync(0xffffffffu, s, j);
            int s1 = __shfl_sync(0xffffffffu, s, j + 1);
            int s2 = __shfl_sync(0xffffffffu, s, j + 2);
            int s3 = __shfl_sync(0xffffffffu, s, j + 3);
            float2 v0 = __ldg((const float2*)(p + (size_t)s0 * 64) + lane);
            float2 v1 = __ldg((const float2*)(p + (size_t)s1 * 64) + lane);
            float2 v2 = __ldg((const float2*)(p + (size_t)s2 * 64) + lane);
            float2 v3 = __ldg((const float2*)(p + (size_t)s3 * 64) + lane);
            ax += v0.x + v1.x + v2.x + v3.x;
            ay += v0.y + v1.y + v2.y + v3.y;
        }
        for (; j < cnt; j++) {
            int sj = __shfl_sync(0xffffffffu, s, j);
            float2 v = __ldg((const float2*)(p + (size_t)sj * 64) + lane);
            ax += v.x; ay += v.y;
        }
    }
    float inv = 1.0f / (float)max(end - beg, 1);
    ((float2*)g_mean)[(size_t)w * 32 + lane] = make_float2(ax * inv, ay * inv);
}

// ---------------- fused dual-GEMM (64->64, f32x2) + L2 normalize -------------
__global__ void __launch_bounds__(256) k_gemm64(const float* __restrict__ hin, int use_gh,
                                                const float* __restrict__ Wl,
                                                const float* __restrict__ Wr,
                                                const float* __restrict__ b) {
    __shared__ __align__(16) float sWl[64 * 64];   // sWl[k*64 + j] = Wl[j][k]
    __shared__ __align__(16) float sWr[64 * 64];
    __shared__ __align__(16) float sb[64];
    for (int i = threadIdx.x; i < 64 * 64; i += 256) {
        int j = i >> 6, k = i & 63;
        sWl[k * 64 + j] = Wl[i];
        sWr[k * 64 + j] = Wr[i];
    }
    if (threadIdx.x < 64) sb[threadIdx.x] = b[threadIdx.x];
    __syncthreads();

    const float* __restrict__ hp = use_gh ? g_h : hin;
    int r = blockIdx.x * 256 + threadIdx.x;
    if (r >= Nn) return;

    ull acc[32];
    const ull* sb2 = (const ull*)sb;
    #pragma unroll
    for (int j2 = 0; j2 < 32; j2++) acc[j2] = sb2[j2];

    const float4* m4 = (const float4*)(g_mean + (size_t)r * 64);
    const float4* h4 = (const float4*)(hp + (size_t)r * 64);
    #pragma unroll 1
    for (int k4 = 0; k4 < 16; k4++) {
        float4 m = __ldg(m4 + k4), h = __ldg(h4 + k4);
        #pragma unroll
        for (int kk = 0; kk < 4; kk++) {
            float mv = kk == 0 ? m.x : kk == 1 ? m.y : kk == 2 ? m.z : m.w;
            float hv = kk == 0 ? h.x : kk == 1 ? h.y : kk == 2 ? h.z : h.w;
            ull mv2 = pack2(mv), hv2 = pack2(hv);
            int k = k4 * 4 + kk;
            const ulonglong2* wl2 = (const ulonglong2*)(sWl + k * 64);
            const ulonglong2* wr2 = (const ulonglong2*)(sWr + k * 64);
            #pragma unroll
            for (int q = 0; q < 16; q++) {
                ulonglong2 a = wl2[q], c = wr2[q];
                acc[q * 2 + 0] = fma2(mv2, a.x, acc[q * 2 + 0]);
                acc[q * 2 + 1] = fma2(mv2, a.y, acc[q * 2 + 1]);
                acc[q * 2 + 0] = fma2(hv2, c.x, acc[q * 2 + 0]);
                acc[q * 2 + 1] = fma2(hv2, c.y, acc[q * 2 + 1]);
            }
        }
    }

    float v[64];
    float s = 0.f;
    #pragma unroll
    for (int j2 = 0; j2 < 32; j2++) {
        float lo, hi;
        unpack2(acc[j2], lo, hi);
        v[j2 * 2] = lo; v[j2 * 2 + 1] = hi;
        s += lo * lo + hi * hi;
    }
    float sc = 1.0f / fmaxf(sqrtf(s), 1e-12f);
    float4* o4 = (float4*)(g_out + (size_t)r * 64);
    #pragma unroll
    for (int j4 = 0; j4 < 16; j4++)
        o4[j4] = make_float4(v[j4 * 4] * sc, v[j4 * 4 + 1] * sc,
                             v[j4 * 4 + 2] * sc, v[j4 * 4 + 3] * sc);
}

// ---------------- batchnorm --------------------------------------------------
__global__ void k_zerobn() {
    if (threadIdx.x < 64) { g_bnsum[threadIdx.x] = 0.f; g_bnsq[threadIdx.x] = 0.f; }
}

__global__ void k_bnstats() {
    int tid = blockIdx.x * blockDim.x + threadIdx.x;
    long long stride = (long long)gridDim.x * blockDim.x;  // multiple of 64
    int col = tid & 63;
    float s = 0.f, q = 0.f;
    for (long long i = tid; i < (long long)Nn * 64; i += stride) {
        float x = g_out[i];
        s += x; q += x * x;
    }
    atomicAdd(&g_bnsum[col], s);
    atomicAdd(&g_bnsq[col], q);
}

__global__ void k_bnapply(const float* __restrict__ gamma, const float* __restrict__ beta) {
    __shared__ float ssc[64], ssh[64];
    if (threadIdx.x < 64) {
        float mu  = g_bnsum[threadIdx.x] * (1.0f / Nn);
        float var = g_bnsq[threadIdx.x] * (1.0f / Nn) - mu * mu;
        float sc  = rsqrtf(var + 1e-5f) * gamma[threadIdx.x];
        ssc[threadIdx.x] = sc;
        ssh[threadIdx.x] = beta[threadIdx.x] - mu * sc;
    }
    __syncthreads();
    long long stride = (long long)gridDim.x * blockDim.x;
    for (long long i = blockIdx.x * (long long)blockDim.x + threadIdx.x;
         i < (long long)Nn * 64; i += stride) {
        int col = (int)(i & 63);
        float y = g_out[i] * ssc[col] + ssh[col];
        g_h[i] = fmaxf(y, 0.0f);
    }
}

// ---------------- layer 3: project FIRST, then aggregate 16-wide -------------
// z[r, 0..15] = h2[r] @ Wl3^T (10 real cols, 6 zero-pad)  -> g_mean (N x 16)
// out[r, 0..9] = h2[r] @ Wr3^T + b3                       -> d_out (partial)
__global__ void __launch_bounds__(256) k_proj3(const float* __restrict__ Wl,
                                               const float* __restrict__ Wr,
                                               const float* __restrict__ b,
                                               float* __restrict__ out) {
    __shared__ float sWl[64 * 10];   // sWl[k*10 + j] = Wl[j][k]
    __shared__ float sWr[64 * 10];
    __shared__ float sb[10];
    for (int i = threadIdx.x; i < 640; i += 256) {
        int j = i / 64, k = i % 64;
        sWl[k * 10 + j] = Wl[i];
        sWr[k * 10 + j] = Wr[i];
    }
    if (threadIdx.x < 10) sb[threadIdx.x] = b[threadIdx.x];
    __syncthreads();

    int r = blockIdx.x * 256 + threadIdx.x;
    if (r >= Nn) return;

    float al[10], ar[10];
    #pragma unroll
    for (int j = 0; j < 10; j++) { al[j] = 0.f; ar[j] = sb[j]; }

    const float4* h4 = (const float4*)(g_h + (size_t)r * 64);
    #pragma unroll 1
    for (int k4 = 0; k4 < 16; k4++) {
        float4 h = __ldg(h4 + k4);
        #pragma unroll
        for (int kk = 0; kk < 4; kk++) {
            float hv = kk == 0 ? h.x : kk == 1 ? h.y : kk == 2 ? h.z : h.w;
            int k = k4 * 4 + kk;
            #pragma unroll
            for (int j = 0; j < 10; j++) {
                al[j] += hv * sWl[k * 10 + j];
                ar[j] += hv * sWr[k * 10 + j];
            }
        }
    }
    float* z = g_mean + (size_t)r * 16;
    #pragma unroll
    for (int j = 0; j < 10; j++) z[j] = al[j];
    #pragma unroll
    for (int j = 10; j < 16; j++) z[j] = 0.f;
    #pragma unroll
    for (int j = 0; j < 10; j++) out[(size_t)r * 10 + j] = ar[j];
}

// mean-aggregate the 16-wide projected rows; add into d_out (has Wr part + b)
__global__ void k_agg10(float* __restrict__ out) {
    int gt = blockIdx.x * blockDim.x + threadIdx.x;
    int w = gt >> 5, lane = gt & 31;
    if (w >= Nn) return;
    int beg = g_rowptr[w], end = g_rowptr[w + 1];
    int half = lane >> 4, col = lane & 15;
    float a = 0.f;
    for (int e = beg + half; e < end; e += 2) {
        int s = __ldg(&g_colidx[e]);
        a += __ldg(&g_mean[(size_t)s * 16 + col]);
    }
    a += __shfl_down_sync(0xffffffffu, a, 16);
    if (lane < 10) {
        float inv = 1.0f / (float)max(end - beg, 1);
        out[(size_t)w * 10 + lane] += a * inv;
    }
}

// ---------------- launch -----------------------------------------------------
extern "C" void kernel_launch(void* const* d_in, const int* in_sizes, int n_in,
                              void* d_out, int out_size) {
    const float* x   = (const float*)d_in[0];
    const void*  ei  = d_in[1];
    const float* Wl1 = (const float*)d_in[2];
    const float* Wr1 = (const float*)d_in[3];
    const float* b1  = (const float*)d_in[4];
    const float* g1  = (const float*)d_in[5];
    const float* be1 = (const float*)d_in[6];
    const float* Wl2 = (const float*)d_in[7];
    const float* Wr2 = (const float*)d_in[8];
    const float* b2  = (const float*)d_in[9];
    const float* g2  = (const float*)d_in[10];
    const float* be2 = (const float*)d_in[11];
    const float* Wl3 = (const float*)d_in[12];
    const float* Wr3 = (const float*)d_in[13];
    const float* b3  = (const float*)d_in[14];
    float* out = (float*)d_out;

    const int NBLK_N   = (Nn + 255) / 256;      // 391
    const int NBLK_AGG = (Nn * 32 + 255) / 256; // 12500
    const int NBLK_E   = 2048;
    const int NBLK_EW  = 592;

    // CSR build
    k_detect     <<<1, 32>>>(ei);
    k_zero_counts<<<NBLK_N, 256>>>();
    k_hist       <<<NBLK_E, 256>>>(ei);
    k_scan1      <<<NSB, 512>>>();
    k_scan2b     <<<1, 256>>>();
    k_scan3      <<<NBLK_N, 256>>>();
    k_fillcur    <<<NBLK_N, 256>>>();
    k_scatter    <<<NBLK_E, 256>>>(ei);

    // Layer 1
    k_agg    <<<NBLK_AGG, 256>>>(x, 0);
    k_gemm64 <<<NBLK_N, 256>>>(x, 0, Wl1, Wr1, b1);
    k_zerobn <<<1, 64>>>();
    k_bnstats<<<NBLK_EW, 256>>>();
    k_bnapply<<<NBLK_EW, 256>>>(g1, be1);

    // Layer 2
    k_agg    <<<NBLK_AGG, 256>>>(nullptr, 1);
    k_gemm64 <<<NBLK_N, 256>>>(nullptr, 1, Wl2, Wr2, b2);
    k_zerobn <<<1, 64>>>();
    k_bnstats<<<NBLK_EW, 256>>>();
    k_bnapply<<<NBLK_EW, 256>>>(g2, be2);

    // Layer 3: project-then-aggregate (linearity of mean)
    k_proj3  <<<NBLK_N, 256>>>(Wl3, Wr3, b3, out);
    k_agg10  <<<NBLK_AGG, 256>>>(out);
}